// round 14
// baseline (speedup 1.0000x reference)
#include <cuda_runtime.h>
#include <cuda_bf16.h>
#include <cstdint>

// ---------------------------------------------------------------------------
// RNN: out[b,t,:] = sigmoid(x@K + h_{t-1}@Wr),  B=64, T=512, D=H=1024
// ONE fused launch, 152 CTAs x 512 threads, hybrid schedule:
//   Phase A: ALL CTAs drain quarter-0 xh tiles (dynamic queue)
//   Phase B: CTAs 0..127 run the recurrence; CTAs 128..151 finish quarters 1..3
// R14: NO grid barrier. Fine-grained dataflow: per-CTA monotonic step flags
//   (g_done[bid] = steps completed). Warp ks polls only its 4 producer CTAs'
//   flags before loading h columns [ks*64, +64). OUT rows are indexed by t,
//   so there is no WAR hazard — producers never overwrite what readers read.
// ---------------------------------------------------------------------------

#define BATCH 64
#define TSEQ  512
#define DIM   1024

#define NCTA_TOTAL 152
#define NPERS      128
#define NTILES     2048
#define TILES_PER_Q 512

// ---- recurrence geometry ----
#define NTILE  16
#define BS_STRIDE 1028
#define BS_WORDS  (NTILE * BS_STRIDE)          // 16448
#define A_STRIDE  68                           // 64 + 4 pad
#define ABUF_WORDS (32 * A_STRIDE)             // 2176: warp buffer 32x64
#define A_REGION_WORDS (16 * ABUF_WORDS)       // 34816
#define FUSED_SMEM_BYTES ((BS_WORDS + A_REGION_WORDS) * 4)   // 205,056 B

// ---- gemm geometry ----
#define G_BM 128
#define G_BN 128
#define G_BK 32
#define GA_STRIDE 36
#define GB_STRIDE 132
#define G_STAGE_WORDS (G_BM * GA_STRIDE + G_BK * GB_STRIDE)   // 8832
#define G_BCAST (2 * G_STAGE_WORDS)

__device__ float g_xh[(size_t)BATCH * TSEQ * DIM];
__device__ unsigned g_tileA;
__device__ unsigned g_tileB;
__device__ unsigned g_qdone[4];
__device__ unsigned g_done[NPERS];   // steps completed per recurrence CTA

__device__ __forceinline__ uint32_t f2tf32(float x) {
    uint32_t r;
    asm("cvt.rna.tf32.f32 %0, %1;" : "=r"(r) : "f"(x));
    return r;
}

__device__ __forceinline__ void mma_tf32(float* d,
                                         uint32_t a0, uint32_t a1, uint32_t a2, uint32_t a3,
                                         uint32_t b0, uint32_t b1) {
    asm volatile(
        "mma.sync.aligned.m16n8k8.row.col.f32.tf32.tf32.f32 "
        "{%0,%1,%2,%3}, {%4,%5,%6,%7}, {%8,%9}, {%0,%1,%2,%3};\n"
        : "+f"(d[0]), "+f"(d[1]), "+f"(d[2]), "+f"(d[3])
        : "r"(a0), "r"(a1), "r"(a2), "r"(a3), "r"(b0), "r"(b1));
}

__device__ __forceinline__ float sigmoidf_fast(float z) {
    return 1.0f / (1.0f + __expf(-z));
}

__device__ __forceinline__ void cp16(uint32_t smem_addr, const void* gsrc) {
    asm volatile("cp.async.cg.shared.global [%0], [%1], 16;\n"
                 :: "r"(smem_addr), "l"(gsrc));
}
__device__ __forceinline__ void cp_commit() {
    asm volatile("cp.async.commit_group;\n" ::: "memory");
}
template <int N>
__device__ __forceinline__ void cp_wait() {
    asm volatile("cp.async.wait_group %0;\n" :: "n"(N) : "memory");
}

// ---------------------------------------------------------------------------
__global__ void reset_state_kernel() {
    if (threadIdx.x < NPERS) g_done[threadIdx.x] = 0u;
    if (threadIdx.x == NPERS + 0) g_tileA = 0u;
    if (threadIdx.x == NPERS + 1) g_tileB = (unsigned)TILES_PER_Q;
    if (threadIdx.x >= NPERS + 2 && threadIdx.x < NPERS + 6)
        g_qdone[threadIdx.x - (NPERS + 2)] = 0u;
}

// ---------------------------------------------------------------------------
// One xh tile: tile = q*512 + b*8 + n -> rows [b*512+q*128, +128), cols n*128.
// ---------------------------------------------------------------------------
__device__ void gemm_tile(uint32_t* gsm, const float* __restrict__ X,
                          const float* __restrict__ W, unsigned tile) {
    const int tid  = threadIdx.x;
    const int lane = tid & 31;
    const int wid  = tid >> 5;
    const int wm   = (wid & 3) * 32;
    const int wn   = (wid >> 2) * 32;
    const int gid  = lane >> 2;
    const int tg   = lane & 3;

    const int q  = (int)(tile >> 9);
    const int j  = (int)(tile & 511);
    const int bm = (j >> 3) * TSEQ + q * 128;
    const int bn = (j & 7) * G_BN;

    auto As = [&](int s) { return gsm + s * G_STAGE_WORDS; };
    auto Bs = [&](int s) { return gsm + s * G_STAGE_WORDS + G_BM * GA_STRIDE; };

    auto issue = [&](int k0, int s) {
        uint32_t abase = (uint32_t)__cvta_generic_to_shared(As(s));
        uint32_t bbase = (uint32_t)__cvta_generic_to_shared(Bs(s));
        #pragma unroll
        for (int i = 0; i < 2; i++) {
            int idx = tid + i * 512;
            int r = idx >> 3;
            int c = (idx & 7) * 4;
            cp16(abase + (r * GA_STRIDE + c) * 4,
                 X + (size_t)(bm + r) * DIM + k0 + c);
        }
        #pragma unroll
        for (int i = 0; i < 2; i++) {
            int idx = tid + i * 512;
            int r = idx >> 5;
            int c = (idx & 31) * 4;
            cp16(bbase + (r * GB_STRIDE + c) * 4,
                 W + (size_t)(k0 + r) * DIM + bn + c);
        }
        cp_commit();
    };

    float acc[2][4][4];
    #pragma unroll
    for (int mt = 0; mt < 2; mt++)
        #pragma unroll
        for (int nt = 0; nt < 4; nt++)
            #pragma unroll
            for (int i = 0; i < 4; i++) acc[mt][nt][i] = 0.0f;

    issue(0, 0);
    issue(G_BK, 1);

    const int NKITER = DIM / G_BK;
    for (int kb = 0; kb < NKITER; kb++) {
        if (kb < NKITER - 1) cp_wait<1>(); else cp_wait<0>();
        __syncthreads();

        const uint32_t* A = As(kb & 1);
        const uint32_t* B = Bs(kb & 1);

        #pragma unroll
        for (int k8 = 0; k8 < G_BK; k8 += 8) {
            uint32_t a[2][4], b[4][2];
            #pragma unroll
            for (int mt = 0; mt < 2; mt++) {
                int r = (wm + mt * 16 + gid) * GA_STRIDE;
                a[mt][0] = A[r + k8 + tg];
                a[mt][1] = A[r + 8 * GA_STRIDE + k8 + tg];
                a[mt][2] = A[r + k8 + tg + 4];
                a[mt][3] = A[r + 8 * GA_STRIDE + k8 + tg + 4];
            }
            #pragma unroll
            for (int nt = 0; nt < 4; nt++) {
                int c = wn + nt * 8 + gid;
                b[nt][0] = B[(k8 + tg) * GB_STRIDE + c];
                b[nt][1] = B[(k8 + tg + 4) * GB_STRIDE + c];
            }
            #pragma unroll
            for (int mt = 0; mt < 2; mt++)
                #pragma unroll
                for (int nt = 0; nt < 4; nt++)
                    mma_tf32(acc[mt][nt], a[mt][0], a[mt][1], a[mt][2], a[mt][3],
                             b[nt][0], b[nt][1]);
        }
        __syncthreads();
        if (kb + 2 < NKITER) issue((kb + 2) * G_BK, kb & 1);
    }

    #pragma unroll
    for (int mt = 0; mt < 2; mt++) {
        #pragma unroll
        for (int nt = 0; nt < 4; nt++) {
            int r = bm + wm + mt * 16 + gid;
            int c = bn + wn + nt * 8 + tg * 2;
            *(float2*)(&g_xh[(size_t)r * DIM + c]) =
                make_float2(acc[mt][nt][0], acc[mt][nt][1]);
            *(float2*)(&g_xh[(size_t)(r + 8) * DIM + c]) =
                make_float2(acc[mt][nt][2], acc[mt][nt][3]);
        }
    }
}

// ---------------------------------------------------------------------------
// Recurrence: CTA bid -> mhalf = bid>>6 (rows [mhalf*32,+32)), bn=(bid&63)*16.
// 16 warps = K-sixteenths (64 cols). B frags in registers; single A buffer.
// DATAFLOW sync: warp ks polls flags of its 4 producer CTAs (cols ks*64..+64),
// CTA publishes g_done[bid]=t+1 after its epilogue. No grid barrier.
// ---------------------------------------------------------------------------
__device__ void pers_path(uint32_t* smem, const float* __restrict__ Wr,
                          float* __restrict__ OUT, int bid) {
    uint32_t* Bsm  = smem;
    uint32_t* Abuf = smem + BS_WORDS;
    float*    Scr  = (float*)Abuf;

    const int tid   = threadIdx.x;
    const int lane  = tid & 31;
    const int wid   = tid >> 5;
    const int mhalf = bid >> 6;
    const int bn    = (bid & 63) * NTILE;
    const int rbase = mhalf * 32;
    const int ks    = wid;
    const int kbase = ks * 64;
    const int gid   = lane >> 2;
    const int tg    = lane & 3;

    // producers of this warp's h columns: 4 CTAs in the same M-half
    const int pbase = (mhalf << 6) + ks * 4;

    // Wr slice -> SMEM transposed [n][k], RNA tf32 (once)
    for (int idx = tid; idx < NTILE * DIM; idx += 512) {
        int n = idx & (NTILE - 1);
        int k = idx >> 4;
        Bsm[n * BS_STRIDE + k] = f2tf32(Wr[(size_t)k * DIM + bn + n]);
    }
    __syncthreads();

    // B fragments -> registers (held for all 512 steps)
    uint32_t breg[8][2][2];
    #pragma unroll
    for (int k8i = 0; k8i < 8; k8i++) {
        #pragma unroll
        for (int nt = 0; nt < 2; nt++) {
            int n = nt * 8 + gid;
            breg[k8i][nt][0] = Bsm[n * BS_STRIDE + kbase + k8i * 8 + tg];
            breg[k8i][nt][1] = Bsm[n * BS_STRIDE + kbase + k8i * 8 + tg + 4];
        }
    }

    // quarter-0 xh must be complete before t=0
    if (tid == 0) {
        unsigned v;
        do {
            asm volatile("ld.acquire.gpu.global.u32 %0, [%1];"
                         : "=r"(v) : "l"(&g_qdone[0]) : "memory");
        } while (v < TILES_PER_Q);
    }
    __syncthreads();

    const uint32_t* Aw = Abuf + wid * ABUF_WORDS;
    const uint32_t warp_sb = (uint32_t)__cvta_generic_to_shared(Abuf)
                           + wid * ABUF_WORDS * 4;

    for (int t = 0; t < TSEQ; t++) {
        if ((t & 127) == 0 && t > 0) {
            if (tid == 0) {
                unsigned v;
                do {
                    asm volatile("ld.acquire.gpu.global.u32 %0, [%1];"
                                 : "=r"(v) : "l"(&g_qdone[t >> 7]) : "memory");
                } while (v < TILES_PER_Q);
            }
            __syncthreads();
        }

        float acc[2][2][4];
        #pragma unroll
        for (int mt = 0; mt < 2; mt++)
            #pragma unroll
            for (int nt = 0; nt < 2; nt++)
                #pragma unroll
                for (int i = 0; i < 4; i++) acc[mt][nt][i] = 0.0f;

        if (t > 0) {
            // ---- dataflow wait: 4 producer CTAs must have completed step t-1
            if (lane < 4) {
                unsigned v;
                do {
                    asm volatile("ld.acquire.gpu.global.u32 %0, [%1];"
                                 : "=r"(v) : "l"(&g_done[pbase + lane]) : "memory");
                } while (v < (unsigned)t);
            }
            __syncwarp();

            const float* Hprev = OUT + (size_t)(t - 1) * DIM;

            // single A load: 32 rows x 64 cols = 16 cp16/lane
            #pragma unroll
            for (int i = 0; i < 16; i++) {
                int idx = lane + i * 32;
                int r  = idx >> 4;
                int c4 = idx & 15;
                cp16(warp_sb + (r * A_STRIDE + c4 * 4) * 4,
                     Hprev + (size_t)(rbase + r) * (TSEQ * DIM) + kbase + c4 * 4);
            }
            cp_commit();
            cp_wait<0>();
            __syncwarp();

            #pragma unroll
            for (int k8i = 0; k8i < 8; k8i++) {
                const int kk = k8i * 8;
                uint32_t a[2][4];
                #pragma unroll
                for (int mt = 0; mt < 2; mt++) {
                    int lr = (mt * 16 + gid) * A_STRIDE;
                    a[mt][0] = Aw[lr + kk + tg];
                    a[mt][1] = Aw[lr + 8 * A_STRIDE + kk + tg];
                    a[mt][2] = Aw[lr + kk + tg + 4];
                    a[mt][3] = Aw[lr + 8 * A_STRIDE + kk + tg + 4];
                }
                #pragma unroll
                for (int nt = 0; nt < 2; nt++) {
                    #pragma unroll
                    for (int mt = 0; mt < 2; mt++)
                        mma_tf32(acc[mt][nt], a[mt][0], a[mt][1], a[mt][2], a[mt][3],
                                 breg[k8i][nt][0], breg[k8i][nt][1]);
                }
            }
        }

        __syncthreads();   // compute done before scratch aliases A buffers

        // partial store: P[ks][row 0..31][col 0..15]
        #pragma unroll
        for (int mt = 0; mt < 2; mt++) {
            int rg = mt * 16 + gid;
            #pragma unroll
            for (int nt = 0; nt < 2; nt++) {
                int off = ks * 512 + rg * 16 + nt * 8 + tg * 2;
                *(float2*)&Scr[off]       = make_float2(acc[mt][nt][0], acc[mt][nt][1]);
                *(float2*)&Scr[off + 128] = make_float2(acc[mt][nt][2], acc[mt][nt][3]);
            }
        }
        __syncthreads();

        // flat epilogue: 512 threads x 1 output
        {
            int o   = tid;
            int row = o >> 4;
            int col = o & 15;
            float s = 0.0f;
            #pragma unroll
            for (int p = 0; p < 16; p++) s += Scr[p * 512 + o];
            size_t go = ((size_t)(rbase + row) * TSEQ + t) * DIM + bn + col;
            OUT[go] = sigmoidf_fast(s + g_xh[go]);
        }

        // publish: all OUT stores visible, then flag step complete.
        // (also orders next iteration's Abuf writes after this step's Scr reads)
        __threadfence();
        __syncthreads();
        if (tid == 0) {
            asm volatile("st.release.gpu.global.u32 [%0], %1;"
                         :: "l"(&g_done[bid]), "r"((unsigned)(t + 1)) : "memory");
        }
    }
}

// ---------------------------------------------------------------------------
__global__ __launch_bounds__(512, 1) void fused_rnn(const float* __restrict__ X,
                                                    const float* __restrict__ W,
                                                    const float* __restrict__ Wr,
                                                    float* __restrict__ OUT) {
    extern __shared__ uint32_t smem[];
    const int tid = threadIdx.x;
    const int bid = blockIdx.x;

    // ---- Phase A: all CTAs drain quarter-0 tiles ----
    for (;;) {
        if (tid == 0) smem[G_BCAST] = atomicAdd(&g_tileA, 1u);
        __syncthreads();
        const unsigned tile = smem[G_BCAST];
        if (tile >= (unsigned)TILES_PER_Q) break;
        gemm_tile(smem, X, W, tile);
        __threadfence();
        __syncthreads();
        if (tid == 0) {
            asm volatile("red.release.gpu.global.add.u32 [%0], %1;"
                         :: "l"(&g_qdone[0]), "r"(1u) : "memory");
        }
    }
    __syncthreads();

    if (bid < NPERS) {
        pers_path(smem, Wr, OUT, bid);
    } else {
        for (;;) {
            if (tid == 0) smem[G_BCAST] = atomicAdd(&g_tileB, 1u);
            __syncthreads();
            const unsigned tile = smem[G_BCAST];
            if (tile >= (unsigned)NTILES) break;
            gemm_tile(smem, X, W, tile);
            __threadfence();
            __syncthreads();
            if (tid == 0) {
                asm volatile("red.release.gpu.global.add.u32 [%0], %1;"
                             :: "l"(&g_qdone[tile >> 9]), "r"(1u) : "memory");
            }
        }
    }
}

// ---------------------------------------------------------------------------
extern "C" void kernel_launch(void* const* d_in, const int* in_sizes, int n_in,
                              void* d_out, int out_size) {
    const float* x  = (const float*)d_in[0];  // [64, 512, 1024]
    const float* w  = (const float*)d_in[1];  // [1024, 1024]
    const float* wr = (const float*)d_in[2];  // [1024, 1024]
    float* out = (float*)d_out;               // [64, 512, 1024]

    cudaFuncSetAttribute(fused_rnn,
                         cudaFuncAttributeMaxDynamicSharedMemorySize,
                         FUSED_SMEM_BYTES);

    reset_state_kernel<<<1, 160>>>();
    fused_rnn<<<NCTA_TOTAL, 512, FUSED_SMEM_BYTES>>>(x, w, wr, out);
}

// round 15
// speedup vs baseline: 1.1907x; 1.1907x over previous
#include <cuda_runtime.h>
#include <cuda_bf16.h>
#include <cstdint>

// ---------------------------------------------------------------------------
// RNN: out[b,t,:] = sigmoid(x@K + h_{t-1}@Wr),  B=64, T=512, D=H=1024
// ONE fused launch, 152 CTAs x 512 threads, hybrid schedule (R13 structure):
//   Phase A: ALL CTAs drain quarter-0 xh tiles; Phase B: CTAs 0..127 run the
//   recurrence (per-half tree barriers); CTAs 128..151 finish quarters 1..3.
// R15: (a) xh prefetched into SMEM via cp.async at step start (DRAM latency
//   hidden behind A load + mma), (b) partials stored into each warp's OWN
//   A-buffer region (syncwarp) -> one fewer __syncthreads per step.
// ---------------------------------------------------------------------------

#define BATCH 64
#define TSEQ  512
#define DIM   1024

#define NCTA_TOTAL 152
#define NPERS      128
#define NTILES     2048
#define TILES_PER_Q 512

// ---- recurrence geometry ----
#define NTILE  16
#define BS_STRIDE 1028
#define BS_WORDS  (NTILE * BS_STRIDE)          // 16448
#define A_STRIDE  68                           // 64 + 4 pad
#define ABUF_WORDS (32 * A_STRIDE)             // 2176: warp buffer 32x64
#define A_REGION_WORDS (16 * ABUF_WORDS)       // 34816
#define XH_WORDS  512                          // per-CTA xh row tile
#define FUSED_SMEM_BYTES ((BS_WORDS + A_REGION_WORDS + XH_WORDS) * 4) // 207,104
 
// ---- gemm geometry ----
#define G_BM 128
#define G_BN 128
#define G_BK 32
#define GA_STRIDE 36
#define GB_STRIDE 132
#define G_STAGE_WORDS (G_BM * GA_STRIDE + G_BK * GB_STRIDE)   // 8832
#define G_BCAST (2 * G_STAGE_WORDS)

__device__ float g_xh[(size_t)BATCH * TSEQ * DIM];
__device__ unsigned g_tileA;
__device__ unsigned g_tileB;
__device__ unsigned g_qdone[4];
__device__ unsigned g_grp[16];
__device__ unsigned g_root[2];
__device__ unsigned g_sense[2];

__device__ __forceinline__ uint32_t f2tf32(float x) {
    uint32_t r;
    asm("cvt.rna.tf32.f32 %0, %1;" : "=r"(r) : "f"(x));
    return r;
}

__device__ __forceinline__ void mma_tf32(float* d,
                                         uint32_t a0, uint32_t a1, uint32_t a2, uint32_t a3,
                                         uint32_t b0, uint32_t b1) {
    asm volatile(
        "mma.sync.aligned.m16n8k8.row.col.f32.tf32.tf32.f32 "
        "{%0,%1,%2,%3}, {%4,%5,%6,%7}, {%8,%9}, {%0,%1,%2,%3};\n"
        : "+f"(d[0]), "+f"(d[1]), "+f"(d[2]), "+f"(d[3])
        : "r"(a0), "r"(a1), "r"(a2), "r"(a3), "r"(b0), "r"(b1));
}

__device__ __forceinline__ float sigmoidf_fast(float z) {
    return 1.0f / (1.0f + __expf(-z));
}

__device__ __forceinline__ void cp16(uint32_t smem_addr, const void* gsrc) {
    asm volatile("cp.async.cg.shared.global [%0], [%1], 16;\n"
                 :: "r"(smem_addr), "l"(gsrc));
}
__device__ __forceinline__ void cp_commit() {
    asm volatile("cp.async.commit_group;\n" ::: "memory");
}
template <int N>
__device__ __forceinline__ void cp_wait() {
    asm volatile("cp.async.wait_group %0;\n" :: "n"(N) : "memory");
}

// ---------------------------------------------------------------------------
__global__ void reset_state_kernel() {
    if (threadIdx.x < 16) g_grp[threadIdx.x] = 0u;
    if (threadIdx.x == 16) g_root[0] = 0u;
    if (threadIdx.x == 17) g_root[1] = 0u;
    if (threadIdx.x == 18) g_sense[0] = 0u;
    if (threadIdx.x == 19) g_sense[1] = 0u;
    if (threadIdx.x == 20) g_tileA = 0u;
    if (threadIdx.x == 21) g_tileB = (unsigned)TILES_PER_Q;
    if (threadIdx.x >= 22 && threadIdx.x < 26) g_qdone[threadIdx.x - 22] = 0u;
}

// ---------------------------------------------------------------------------
// Per-M-half tree barrier over 64 CTAs: 8 groups of 8 -> root of 8.
// ---------------------------------------------------------------------------
__device__ __forceinline__ void half_barrier(int bid, int tid, int t) {
    __syncthreads();
    if (tid == 0) {
        const int half = bid >> 6;
        const unsigned ns = ((unsigned)t & 1u) ^ 1u;
        __threadfence();
        unsigned old;
        asm volatile("atom.acq_rel.gpu.global.add.u32 %0, [%1], %2;"
                     : "=r"(old) : "l"(&g_grp[bid >> 3]), "r"(1u) : "memory");
        if (old == 7u) {
            asm volatile("st.relaxed.gpu.global.u32 [%0], %1;"
                         :: "l"(&g_grp[bid >> 3]), "r"(0u) : "memory");
            unsigned rold;
            asm volatile("atom.acq_rel.gpu.global.add.u32 %0, [%1], %2;"
                         : "=r"(rold) : "l"(&g_root[half]), "r"(1u) : "memory");
            if (rold == 7u) {
                asm volatile("st.relaxed.gpu.global.u32 [%0], %1;"
                             :: "l"(&g_root[half]), "r"(0u) : "memory");
                asm volatile("st.release.gpu.global.u32 [%0], %1;"
                             :: "l"(&g_sense[half]), "r"(ns) : "memory");
            } else {
                unsigned v;
                do {
                    asm volatile("ld.acquire.gpu.global.u32 %0, [%1];"
                                 : "=r"(v) : "l"(&g_sense[half]) : "memory");
                } while (v != ns);
            }
        } else {
            unsigned v;
            do {
                asm volatile("ld.acquire.gpu.global.u32 %0, [%1];"
                             : "=r"(v) : "l"(&g_sense[half]) : "memory");
            } while (v != ns);
        }
    }
    __syncthreads();
}

// ---------------------------------------------------------------------------
// One xh tile: tile = q*512 + b*8 + n -> rows [b*512+q*128, +128), cols n*128.
// ---------------------------------------------------------------------------
__device__ void gemm_tile(uint32_t* gsm, const float* __restrict__ X,
                          const float* __restrict__ W, unsigned tile) {
    const int tid  = threadIdx.x;
    const int lane = tid & 31;
    const int wid  = tid >> 5;
    const int wm   = (wid & 3) * 32;
    const int wn   = (wid >> 2) * 32;
    const int gid  = lane >> 2;
    const int tg   = lane & 3;

    const int q  = (int)(tile >> 9);
    const int j  = (int)(tile & 511);
    const int bm = (j >> 3) * TSEQ + q * 128;
    const int bn = (j & 7) * G_BN;

    auto As = [&](int s) { return gsm + s * G_STAGE_WORDS; };
    auto Bs = [&](int s) { return gsm + s * G_STAGE_WORDS + G_BM * GA_STRIDE; };

    auto issue = [&](int k0, int s) {
        uint32_t abase = (uint32_t)__cvta_generic_to_shared(As(s));
        uint32_t bbase = (uint32_t)__cvta_generic_to_shared(Bs(s));
        #pragma unroll
        for (int i = 0; i < 2; i++) {
            int idx = tid + i * 512;
            int r = idx >> 3;
            int c = (idx & 7) * 4;
            cp16(abase + (r * GA_STRIDE + c) * 4,
                 X + (size_t)(bm + r) * DIM + k0 + c);
        }
        #pragma unroll
        for (int i = 0; i < 2; i++) {
            int idx = tid + i * 512;
            int r = idx >> 5;
            int c = (idx & 31) * 4;
            cp16(bbase + (r * GB_STRIDE + c) * 4,
                 W + (size_t)(k0 + r) * DIM + bn + c);
        }
        cp_commit();
    };

    float acc[2][4][4];
    #pragma unroll
    for (int mt = 0; mt < 2; mt++)
        #pragma unroll
        for (int nt = 0; nt < 4; nt++)
            #pragma unroll
            for (int i = 0; i < 4; i++) acc[mt][nt][i] = 0.0f;

    issue(0, 0);
    issue(G_BK, 1);

    const int NKITER = DIM / G_BK;
    for (int kb = 0; kb < NKITER; kb++) {
        if (kb < NKITER - 1) cp_wait<1>(); else cp_wait<0>();
        __syncthreads();

        const uint32_t* A = As(kb & 1);
        const uint32_t* B = Bs(kb & 1);

        #pragma unroll
        for (int k8 = 0; k8 < G_BK; k8 += 8) {
            uint32_t a[2][4], b[4][2];
            #pragma unroll
            for (int mt = 0; mt < 2; mt++) {
                int r = (wm + mt * 16 + gid) * GA_STRIDE;
                a[mt][0] = A[r + k8 + tg];
                a[mt][1] = A[r + 8 * GA_STRIDE + k8 + tg];
                a[mt][2] = A[r + k8 + tg + 4];
                a[mt][3] = A[r + 8 * GA_STRIDE + k8 + tg + 4];
            }
            #pragma unroll
            for (int nt = 0; nt < 4; nt++) {
                int c = wn + nt * 8 + gid;
                b[nt][0] = B[(k8 + tg) * GB_STRIDE + c];
                b[nt][1] = B[(k8 + tg + 4) * GB_STRIDE + c];
            }
            #pragma unroll
            for (int mt = 0; mt < 2; mt++)
                #pragma unroll
                for (int nt = 0; nt < 4; nt++)
                    mma_tf32(acc[mt][nt], a[mt][0], a[mt][1], a[mt][2], a[mt][3],
                             b[nt][0], b[nt][1]);
        }
        __syncthreads();
        if (kb + 2 < NKITER) issue((kb + 2) * G_BK, kb & 1);
    }

    #pragma unroll
    for (int mt = 0; mt < 2; mt++) {
        #pragma unroll
        for (int nt = 0; nt < 4; nt++) {
            int r = bm + wm + mt * 16 + gid;
            int c = bn + wn + nt * 8 + tg * 2;
            *(float2*)(&g_xh[(size_t)r * DIM + c]) =
                make_float2(acc[mt][nt][0], acc[mt][nt][1]);
            *(float2*)(&g_xh[(size_t)(r + 8) * DIM + c]) =
                make_float2(acc[mt][nt][2], acc[mt][nt][3]);
        }
    }
}

// ---------------------------------------------------------------------------
// Recurrence: CTA bid -> mhalf = bid>>6 (rows [mhalf*32,+32)), bn=(bid&63)*16.
// 16 warps = K-sixteenths. B frags in registers; single A buffer per warp.
// Step: prefetch xh (cp.async) + A load -> mma -> partials into OWN A region
// (syncwarp) -> one syncthreads -> epilogue (xh from SMEM) -> tree barrier.
// ---------------------------------------------------------------------------
__device__ void pers_path(uint32_t* smem, const float* __restrict__ Wr,
                          float* __restrict__ OUT, int bid) {
    uint32_t* Bsm  = smem;
    uint32_t* Abuf = smem + BS_WORDS;
    float*    Prt  = (float*)Abuf;               // partials live in A region
    float*    Xhs  = (float*)(smem + BS_WORDS + A_REGION_WORDS);  // 512 floats

    const int tid   = threadIdx.x;
    const int lane  = tid & 31;
    const int wid   = tid >> 5;
    const int mhalf = bid >> 6;
    const int bn    = (bid & 63) * NTILE;
    const int rbase = mhalf * 32;
    const int ks    = wid;
    const int kbase = ks * 64;
    const int gid   = lane >> 2;
    const int tg    = lane & 3;

    // Wr slice -> SMEM transposed [n][k], RNA tf32 (once)
    for (int idx = tid; idx < NTILE * DIM; idx += 512) {
        int n = idx & (NTILE - 1);
        int k = idx >> 4;
        Bsm[n * BS_STRIDE + k] = f2tf32(Wr[(size_t)k * DIM + bn + n]);
    }
    __syncthreads();

    // B fragments -> registers (held for all 512 steps)
    uint32_t breg[8][2][2];
    #pragma unroll
    for (int k8i = 0; k8i < 8; k8i++) {
        #pragma unroll
        for (int nt = 0; nt < 2; nt++) {
            int n = nt * 8 + gid;
            breg[k8i][nt][0] = Bsm[n * BS_STRIDE + kbase + k8i * 8 + tg];
            breg[k8i][nt][1] = Bsm[n * BS_STRIDE + kbase + k8i * 8 + tg + 4];
        }
    }

    // quarter-0 xh complete before t=0
    if (tid == 0) {
        unsigned v;
        do {
            asm volatile("ld.acquire.gpu.global.u32 %0, [%1];"
                         : "=r"(v) : "l"(&g_qdone[0]) : "memory");
        } while (v < TILES_PER_Q);
    }
    __syncthreads();

    const uint32_t* Aw = Abuf + wid * ABUF_WORDS;
    const uint32_t warp_sb = (uint32_t)__cvta_generic_to_shared(Abuf)
                           + wid * ABUF_WORDS * 4;
    const uint32_t xh_sb = (uint32_t)__cvta_generic_to_shared(Xhs);

    for (int t = 0; t < TSEQ; t++) {
        if ((t & 127) == 0 && t > 0) {
            if (tid == 0) {
                unsigned v;
                do {
                    asm volatile("ld.acquire.gpu.global.u32 %0, [%1];"
                                 : "=r"(v) : "l"(&g_qdone[t >> 7]) : "memory");
                } while (v < TILES_PER_Q);
            }
            __syncthreads();
        }

        float acc[2][2][4];
        #pragma unroll
        for (int mt = 0; mt < 2; mt++)
            #pragma unroll
            for (int nt = 0; nt < 2; nt++)
                #pragma unroll
                for (int i = 0; i < 4; i++) acc[mt][nt][i] = 0.0f;

        if (t > 0) {
            const float* Hprev = OUT + (size_t)(t - 1) * DIM;

            // xh prefetch for THIS step: 512 floats = 128 cp16 (threads 0-127).
            // Hidden behind the A load + mma below; consumed in the epilogue.
            if (tid < 128) {
                int row = tid >> 2;         // 0..31
                int seg = (tid & 3) * 4;    // 0,4,8,12
                cp16(xh_sb + (row * 16 + seg) * 4,
                     &g_xh[((size_t)(rbase + row) * TSEQ + t) * DIM + bn + seg]);
            }

            // A load: 32 rows x 64 cols = 16 cp16/lane
            #pragma unroll
            for (int i = 0; i < 16; i++) {
                int idx = lane + i * 32;
                int r  = idx >> 4;
                int c4 = idx & 15;
                cp16(warp_sb + (r * A_STRIDE + c4 * 4) * 4,
                     Hprev + (size_t)(rbase + r) * (TSEQ * DIM) + kbase + c4 * 4);
            }
            cp_commit();
            cp_wait<0>();
            __syncwarp();

            #pragma unroll
            for (int k8i = 0; k8i < 8; k8i++) {
                const int kk = k8i * 8;
                uint32_t a[2][4];
                #pragma unroll
                for (int mt = 0; mt < 2; mt++) {
                    int lr = (mt * 16 + gid) * A_STRIDE;
                    a[mt][0] = Aw[lr + kk + tg];
                    a[mt][1] = Aw[lr + 8 * A_STRIDE + kk + tg];
                    a[mt][2] = Aw[lr + kk + tg + 4];
                    a[mt][3] = Aw[lr + 8 * A_STRIDE + kk + tg + 4];
                }
                #pragma unroll
                for (int nt = 0; nt < 2; nt++) {
                    #pragma unroll
                    for (int mt = 0; mt < 2; mt++)
                        mma_tf32(acc[mt][nt], a[mt][0], a[mt][1], a[mt][2], a[mt][3],
                                 breg[k8i][nt][0], breg[k8i][nt][1]);
                }
            }
        }

        // partial store into THIS warp's own A region (warp-private -> syncwarp)
        __syncwarp();
        #pragma unroll
        for (int mt = 0; mt < 2; mt++) {
            int rg = mt * 16 + gid;
            #pragma unroll
            for (int nt = 0; nt < 2; nt++) {
                int off = wid * ABUF_WORDS + rg * 16 + nt * 8 + tg * 2;
                *(float2*)&Prt[off]       = make_float2(acc[mt][nt][0], acc[mt][nt][1]);
                *(float2*)&Prt[off + 128] = make_float2(acc[mt][nt][2], acc[mt][nt][3]);
            }
        }
        __syncthreads();

        // flat epilogue: 512 threads x 1 output; xh from SMEM (t>0)
        {
            int o   = tid;
            int row = o >> 4;
            int col = o & 15;
            float s = 0.0f;
            #pragma unroll
            for (int p = 0; p < 16; p++) s += Prt[p * ABUF_WORDS + o];
            size_t go = ((size_t)(rbase + row) * TSEQ + t) * DIM + bn + col;
            float xh = (t > 0) ? Xhs[o] : g_xh[go];
            OUT[go] = sigmoidf_fast(s + xh);
        }

        half_barrier(bid, tid, t);
    }
}

// ---------------------------------------------------------------------------
__global__ __launch_bounds__(512, 1) void fused_rnn(const float* __restrict__ X,
                                                    const float* __restrict__ W,
                                                    const float* __restrict__ Wr,
                                                    float* __restrict__ OUT) {
    extern __shared__ uint32_t smem[];
    const int tid = threadIdx.x;
    const int bid = blockIdx.x;

    // ---- Phase A: all CTAs drain quarter-0 tiles ----
    for (;;) {
        if (tid == 0) smem[G_BCAST] = atomicAdd(&g_tileA, 1u);
        __syncthreads();
        const unsigned tile = smem[G_BCAST];
        if (tile >= (unsigned)TILES_PER_Q) break;
        gemm_tile(smem, X, W, tile);
        __threadfence();
        __syncthreads();
        if (tid == 0) {
            asm volatile("red.release.gpu.global.add.u32 [%0], %1;"
                         :: "l"(&g_qdone[0]), "r"(1u) : "memory");
        }
    }
    __syncthreads();

    if (bid < NPERS) {
        pers_path(smem, Wr, OUT, bid);
    } else {
        for (;;) {
            if (tid == 0) smem[G_BCAST] = atomicAdd(&g_tileB, 1u);
            __syncthreads();
            const unsigned tile = smem[G_BCAST];
            if (tile >= (unsigned)NTILES) break;
            gemm_tile(smem, X, W, tile);
            __threadfence();
            __syncthreads();
            if (tid == 0) {
                asm volatile("red.release.gpu.global.add.u32 [%0], %1;"
                             :: "l"(&g_qdone[tile >> 9]), "r"(1u) : "memory");
            }
        }
    }
}

// ---------------------------------------------------------------------------
extern "C" void kernel_launch(void* const* d_in, const int* in_sizes, int n_in,
                              void* d_out, int out_size) {
    const float* x  = (const float*)d_in[0];  // [64, 512, 1024]
    const float* w  = (const float*)d_in[1];  // [1024, 1024]
    const float* wr = (const float*)d_in[2];  // [1024, 1024]
    float* out = (float*)d_out;               // [64, 512, 1024]

    cudaFuncSetAttribute(fused_rnn,
                         cudaFuncAttributeMaxDynamicSharedMemorySize,
                         FUSED_SMEM_BYTES);

    reset_state_kernel<<<1, 32>>>();
    fused_rnn<<<NCTA_TOTAL, 512, FUSED_SMEM_BYTES>>>(x, w, wr, out);
}

// round 16
// speedup vs baseline: 1.7689x; 1.4857x over previous
#include <cuda_runtime.h>
#include <cuda_bf16.h>
#include <cstdint>

// ---------------------------------------------------------------------------
// RNN: out[b,t,:] = sigmoid(x@K + h_{t-1}@Wr),  B=64, T=512, D=H=1024
// ONE fused launch, 152 CTAs x 512 threads (R13 structure):
//   Phase A: ALL CTAs drain quarter-0 xh tiles; Phase B: CTAs 0..127 run the
//   recurrence (per-half tree barriers); CTAs 128..151 finish quarters 1..3.
// R16 = R13 + xh prefetch in a SEPARATE cp.async group:
//   group1 = A tile (waited before mma), group2 = xh tile (waited after mma,
//   DRAM latency hidden behind the 32-mma block). Epilogue reads xh from SMEM.
// ---------------------------------------------------------------------------

#define BATCH 64
#define TSEQ  512
#define DIM   1024

#define NCTA_TOTAL 152
#define NPERS      128
#define NTILES     2048
#define TILES_PER_Q 512

// ---- recurrence geometry ----
#define NTILE  16
#define BS_STRIDE 1028
#define BS_WORDS  (NTILE * BS_STRIDE)          // 16448
#define A_STRIDE  68                           // 64 + 4 pad
#define ABUF_WORDS (32 * A_STRIDE)             // 2176: warp buffer 32x64
#define A_REGION_WORDS (16 * ABUF_WORDS)       // 34816
#define XH_WORDS  512
#define FUSED_SMEM_BYTES ((BS_WORDS + A_REGION_WORDS + XH_WORDS) * 4) // 207,104

// ---- gemm geometry ----
#define G_BM 128
#define G_BN 128
#define G_BK 32
#define GA_STRIDE 36
#define GB_STRIDE 132
#define G_STAGE_WORDS (G_BM * GA_STRIDE + G_BK * GB_STRIDE)   // 8832
#define G_BCAST (2 * G_STAGE_WORDS)

__device__ float g_xh[(size_t)BATCH * TSEQ * DIM];
__device__ unsigned g_tileA;
__device__ unsigned g_tileB;
__device__ unsigned g_qdone[4];
__device__ unsigned g_grp[16];
__device__ unsigned g_root[2];
__device__ unsigned g_sense[2];

__device__ __forceinline__ uint32_t f2tf32(float x) {
    uint32_t r;
    asm("cvt.rna.tf32.f32 %0, %1;" : "=r"(r) : "f"(x));
    return r;
}

__device__ __forceinline__ void mma_tf32(float* d,
                                         uint32_t a0, uint32_t a1, uint32_t a2, uint32_t a3,
                                         uint32_t b0, uint32_t b1) {
    asm volatile(
        "mma.sync.aligned.m16n8k8.row.col.f32.tf32.tf32.f32 "
        "{%0,%1,%2,%3}, {%4,%5,%6,%7}, {%8,%9}, {%0,%1,%2,%3};\n"
        : "+f"(d[0]), "+f"(d[1]), "+f"(d[2]), "+f"(d[3])
        : "r"(a0), "r"(a1), "r"(a2), "r"(a3), "r"(b0), "r"(b1));
}

__device__ __forceinline__ float sigmoidf_fast(float z) {
    return 1.0f / (1.0f + __expf(-z));
}

__device__ __forceinline__ void cp16(uint32_t smem_addr, const void* gsrc) {
    asm volatile("cp.async.cg.shared.global [%0], [%1], 16;\n"
                 :: "r"(smem_addr), "l"(gsrc));
}
__device__ __forceinline__ void cp_commit() {
    asm volatile("cp.async.commit_group;\n" ::: "memory");
}
template <int N>
__device__ __forceinline__ void cp_wait() {
    asm volatile("cp.async.wait_group %0;\n" :: "n"(N) : "memory");
}

// ---------------------------------------------------------------------------
__global__ void reset_state_kernel() {
    if (threadIdx.x < 16) g_grp[threadIdx.x] = 0u;
    if (threadIdx.x == 16) g_root[0] = 0u;
    if (threadIdx.x == 17) g_root[1] = 0u;
    if (threadIdx.x == 18) g_sense[0] = 0u;
    if (threadIdx.x == 19) g_sense[1] = 0u;
    if (threadIdx.x == 20) g_tileA = 0u;
    if (threadIdx.x == 21) g_tileB = (unsigned)TILES_PER_Q;
    if (threadIdx.x >= 22 && threadIdx.x < 26) g_qdone[threadIdx.x - 22] = 0u;
}

// ---------------------------------------------------------------------------
// Per-M-half tree barrier over 64 CTAs: 8 groups of 8 -> root of 8.
// ---------------------------------------------------------------------------
__device__ __forceinline__ void half_barrier(int bid, int tid, int t) {
    __syncthreads();
    if (tid == 0) {
        const int half = bid >> 6;
        const unsigned ns = ((unsigned)t & 1u) ^ 1u;
        __threadfence();
        unsigned old;
        asm volatile("atom.acq_rel.gpu.global.add.u32 %0, [%1], %2;"
                     : "=r"(old) : "l"(&g_grp[bid >> 3]), "r"(1u) : "memory");
        if (old == 7u) {
            asm volatile("st.relaxed.gpu.global.u32 [%0], %1;"
                         :: "l"(&g_grp[bid >> 3]), "r"(0u) : "memory");
            unsigned rold;
            asm volatile("atom.acq_rel.gpu.global.add.u32 %0, [%1], %2;"
                         : "=r"(rold) : "l"(&g_root[half]), "r"(1u) : "memory");
            if (rold == 7u) {
                asm volatile("st.relaxed.gpu.global.u32 [%0], %1;"
                             :: "l"(&g_root[half]), "r"(0u) : "memory");
                asm volatile("st.release.gpu.global.u32 [%0], %1;"
                             :: "l"(&g_sense[half]), "r"(ns) : "memory");
            } else {
                unsigned v;
                do {
                    asm volatile("ld.acquire.gpu.global.u32 %0, [%1];"
                                 : "=r"(v) : "l"(&g_sense[half]) : "memory");
                } while (v != ns);
            }
        } else {
            unsigned v;
            do {
                asm volatile("ld.acquire.gpu.global.u32 %0, [%1];"
                             : "=r"(v) : "l"(&g_sense[half]) : "memory");
            } while (v != ns);
        }
    }
    __syncthreads();
}

// ---------------------------------------------------------------------------
// One xh tile: tile = q*512 + b*8 + n -> rows [b*512+q*128, +128), cols n*128.
// ---------------------------------------------------------------------------
__device__ void gemm_tile(uint32_t* gsm, const float* __restrict__ X,
                          const float* __restrict__ W, unsigned tile) {
    const int tid  = threadIdx.x;
    const int lane = tid & 31;
    const int wid  = tid >> 5;
    const int wm   = (wid & 3) * 32;
    const int wn   = (wid >> 2) * 32;
    const int gid  = lane >> 2;
    const int tg   = lane & 3;

    const int q  = (int)(tile >> 9);
    const int j  = (int)(tile & 511);
    const int bm = (j >> 3) * TSEQ + q * 128;
    const int bn = (j & 7) * G_BN;

    auto As = [&](int s) { return gsm + s * G_STAGE_WORDS; };
    auto Bs = [&](int s) { return gsm + s * G_STAGE_WORDS + G_BM * GA_STRIDE; };

    auto issue = [&](int k0, int s) {
        uint32_t abase = (uint32_t)__cvta_generic_to_shared(As(s));
        uint32_t bbase = (uint32_t)__cvta_generic_to_shared(Bs(s));
        #pragma unroll
        for (int i = 0; i < 2; i++) {
            int idx = tid + i * 512;
            int r = idx >> 3;
            int c = (idx & 7) * 4;
            cp16(abase + (r * GA_STRIDE + c) * 4,
                 X + (size_t)(bm + r) * DIM + k0 + c);
        }
        #pragma unroll
        for (int i = 0; i < 2; i++) {
            int idx = tid + i * 512;
            int r = idx >> 5;
            int c = (idx & 31) * 4;
            cp16(bbase + (r * GB_STRIDE + c) * 4,
                 W + (size_t)(k0 + r) * DIM + bn + c);
        }
        cp_commit();
    };

    float acc[2][4][4];
    #pragma unroll
    for (int mt = 0; mt < 2; mt++)
        #pragma unroll
        for (int nt = 0; nt < 4; nt++)
            #pragma unroll
            for (int i = 0; i < 4; i++) acc[mt][nt][i] = 0.0f;

    issue(0, 0);
    issue(G_BK, 1);

    const int NKITER = DIM / G_BK;
    for (int kb = 0; kb < NKITER; kb++) {
        if (kb < NKITER - 1) cp_wait<1>(); else cp_wait<0>();
        __syncthreads();

        const uint32_t* A = As(kb & 1);
        const uint32_t* B = Bs(kb & 1);

        #pragma unroll
        for (int k8 = 0; k8 < G_BK; k8 += 8) {
            uint32_t a[2][4], b[4][2];
            #pragma unroll
            for (int mt = 0; mt < 2; mt++) {
                int r = (wm + mt * 16 + gid) * GA_STRIDE;
                a[mt][0] = A[r + k8 + tg];
                a[mt][1] = A[r + 8 * GA_STRIDE + k8 + tg];
                a[mt][2] = A[r + k8 + tg + 4];
                a[mt][3] = A[r + 8 * GA_STRIDE + k8 + tg + 4];
            }
            #pragma unroll
            for (int nt = 0; nt < 4; nt++) {
                int c = wn + nt * 8 + gid;
                b[nt][0] = B[(k8 + tg) * GB_STRIDE + c];
                b[nt][1] = B[(k8 + tg + 4) * GB_STRIDE + c];
            }
            #pragma unroll
            for (int mt = 0; mt < 2; mt++)
                #pragma unroll
                for (int nt = 0; nt < 4; nt++)
                    mma_tf32(acc[mt][nt], a[mt][0], a[mt][1], a[mt][2], a[mt][3],
                             b[nt][0], b[nt][1]);
        }
        __syncthreads();
        if (kb + 2 < NKITER) issue((kb + 2) * G_BK, kb & 1);
    }

    #pragma unroll
    for (int mt = 0; mt < 2; mt++) {
        #pragma unroll
        for (int nt = 0; nt < 4; nt++) {
            int r = bm + wm + mt * 16 + gid;
            int c = bn + wn + nt * 8 + tg * 2;
            *(float2*)(&g_xh[(size_t)r * DIM + c]) =
                make_float2(acc[mt][nt][0], acc[mt][nt][1]);
            *(float2*)(&g_xh[(size_t)(r + 8) * DIM + c]) =
                make_float2(acc[mt][nt][2], acc[mt][nt][3]);
        }
    }
}

// ---------------------------------------------------------------------------
// Recurrence (R13 interior): CTA bid -> mhalf = bid>>6, bn = (bid&63)*16.
// 16 warps = K-sixteenths. B frags in registers; single A buffer per warp.
// Step: [A cp group1 | xh cp group2] -> wait<1> -> mma -> wait<0> ->
//       syncthreads -> partials to Scr -> syncthreads -> epilogue(SMEM xh)
//       -> per-half tree barrier.
// ---------------------------------------------------------------------------
__device__ void pers_path(uint32_t* smem, const float* __restrict__ Wr,
                          float* __restrict__ OUT, int bid) {
    uint32_t* Bsm  = smem;
    uint32_t* Abuf = smem + BS_WORDS;
    float*    Scr  = (float*)Abuf;
    float*    Xhs  = (float*)(smem + BS_WORDS + A_REGION_WORDS);

    const int tid   = threadIdx.x;
    const int lane  = tid & 31;
    const int wid   = tid >> 5;
    const int mhalf = bid >> 6;
    const int bn    = (bid & 63) * NTILE;
    const int rbase = mhalf * 32;
    const int ks    = wid;
    const int kbase = ks * 64;
    const int gid   = lane >> 2;
    const int tg    = lane & 3;

    // Wr slice -> SMEM transposed [n][k], RNA tf32 (once)
    for (int idx = tid; idx < NTILE * DIM; idx += 512) {
        int n = idx & (NTILE - 1);
        int k = idx >> 4;
        Bsm[n * BS_STRIDE + k] = f2tf32(Wr[(size_t)k * DIM + bn + n]);
    }
    __syncthreads();

    // B fragments -> registers (held for all 512 steps)
    uint32_t breg[8][2][2];
    #pragma unroll
    for (int k8i = 0; k8i < 8; k8i++) {
        #pragma unroll
        for (int nt = 0; nt < 2; nt++) {
            int n = nt * 8 + gid;
            breg[k8i][nt][0] = Bsm[n * BS_STRIDE + kbase + k8i * 8 + tg];
            breg[k8i][nt][1] = Bsm[n * BS_STRIDE + kbase + k8i * 8 + tg + 4];
        }
    }

    // quarter-0 xh complete before t=0
    if (tid == 0) {
        unsigned v;
        do {
            asm volatile("ld.acquire.gpu.global.u32 %0, [%1];"
                         : "=r"(v) : "l"(&g_qdone[0]) : "memory");
        } while (v < TILES_PER_Q);
    }
    __syncthreads();

    const uint32_t* Aw = Abuf + wid * ABUF_WORDS;
    const uint32_t warp_sb = (uint32_t)__cvta_generic_to_shared(Abuf)
                           + wid * ABUF_WORDS * 4;
    const uint32_t xh_sb = (uint32_t)__cvta_generic_to_shared(Xhs);

    for (int t = 0; t < TSEQ; t++) {
        if ((t & 127) == 0 && t > 0) {
            if (tid == 0) {
                unsigned v;
                do {
                    asm volatile("ld.acquire.gpu.global.u32 %0, [%1];"
                                 : "=r"(v) : "l"(&g_qdone[t >> 7]) : "memory");
                } while (v < TILES_PER_Q);
            }
            __syncthreads();
        }

        float acc[2][2][4];
        #pragma unroll
        for (int mt = 0; mt < 2; mt++)
            #pragma unroll
            for (int nt = 0; nt < 2; nt++)
                #pragma unroll
                for (int i = 0; i < 4; i++) acc[mt][nt][i] = 0.0f;

        if (t > 0) {
            const float* Hprev = OUT + (size_t)(t - 1) * DIM;

            // GROUP 1: A load (32 rows x 64 cols = 16 cp16/lane)
            #pragma unroll
            for (int i = 0; i < 16; i++) {
                int idx = lane + i * 32;
                int r  = idx >> 4;
                int c4 = idx & 15;
                cp16(warp_sb + (r * A_STRIDE + c4 * 4) * 4,
                     Hprev + (size_t)(rbase + r) * (TSEQ * DIM) + kbase + c4 * 4);
            }
            cp_commit();

            // GROUP 2: xh prefetch (128 cp16; lanes 0-7 of every warp issue 1).
            // Every thread commits group 2 (empty for lanes >= 8) so per-thread
            // group counts stay uniform for the waits below.
            if (lane < 8) {
                int idx = wid * 8 + lane;    // 0..127
                int row = idx >> 2;          // 0..31
                int seg = (idx & 3) * 4;     // 0,4,8,12
                cp16(xh_sb + (row * 16 + seg) * 4,
                     &g_xh[((size_t)(rbase + row) * TSEQ + t) * DIM + bn + seg]);
            }
            cp_commit();

            cp_wait<1>();    // A landed; xh (DRAM) still in flight behind mma
            __syncwarp();

            #pragma unroll
            for (int k8i = 0; k8i < 8; k8i++) {
                const int kk = k8i * 8;
                uint32_t a[2][4];
                #pragma unroll
                for (int mt = 0; mt < 2; mt++) {
                    int lr = (mt * 16 + gid) * A_STRIDE;
                    a[mt][0] = Aw[lr + kk + tg];
                    a[mt][1] = Aw[lr + 8 * A_STRIDE + kk + tg];
                    a[mt][2] = Aw[lr + kk + tg + 4];
                    a[mt][3] = Aw[lr + 8 * A_STRIDE + kk + tg + 4];
                }
                #pragma unroll
                for (int nt = 0; nt < 2; nt++) {
                    #pragma unroll
                    for (int mt = 0; mt < 2; mt++)
                        mma_tf32(acc[mt][nt], a[mt][0], a[mt][1], a[mt][2], a[mt][3],
                                 breg[k8i][nt][0], breg[k8i][nt][1]);
                }
            }

            cp_wait<0>();    // xh landed (hidden behind the 32-mma block)
        }

        __syncthreads();   // compute done before scratch aliases A buffers

        // partial store: P[ks][row 0..31][col 0..15]  (R13 layout)
        #pragma unroll
        for (int mt = 0; mt < 2; mt++) {
            int rg = mt * 16 + gid;
            #pragma unroll
            for (int nt = 0; nt < 2; nt++) {
                int off = ks * 512 + rg * 16 + nt * 8 + tg * 2;
                *(float2*)&Scr[off]       = make_float2(acc[mt][nt][0], acc[mt][nt][1]);
                *(float2*)&Scr[off + 128] = make_float2(acc[mt][nt][2], acc[mt][nt][3]);
            }
        }
        __syncthreads();

        // flat epilogue: 512 threads x 1 output; xh from SMEM (t>0)
        {
            int o   = tid;
            int row = o >> 4;
            int col = o & 15;
            float s = 0.0f;
            #pragma unroll
            for (int p = 0; p < 16; p++) s += Scr[p * 512 + o];
            size_t go = ((size_t)(rbase + row) * TSEQ + t) * DIM + bn + col;
            float xh = (t > 0) ? Xhs[o] : g_xh[go];
            OUT[go] = sigmoidf_fast(s + xh);
        }

        half_barrier(bid, tid, t);
    }
}

// ---------------------------------------------------------------------------
__global__ __launch_bounds__(512, 1) void fused_rnn(const float* __restrict__ X,
                                                    const float* __restrict__ W,
                                                    const float* __restrict__ Wr,
                                                    float* __restrict__ OUT) {
    extern __shared__ uint32_t smem[];
    const int tid = threadIdx.x;
    const int bid = blockIdx.x;

    // ---- Phase A: all CTAs drain quarter-0 tiles ----
    for (;;) {
        if (tid == 0) smem[G_BCAST] = atomicAdd(&g_tileA, 1u);
        __syncthreads();
        const unsigned tile = smem[G_BCAST];
        if (tile >= (unsigned)TILES_PER_Q) break;
        gemm_tile(smem, X, W, tile);
        __threadfence();
        __syncthreads();
        if (tid == 0) {
            asm volatile("red.release.gpu.global.add.u32 [%0], %1;"
                         :: "l"(&g_qdone[0]), "r"(1u) : "memory");
        }
    }
    __syncthreads();

    if (bid < NPERS) {
        pers_path(smem, Wr, OUT, bid);
    } else {
        for (;;) {
            if (tid == 0) smem[G_BCAST] = atomicAdd(&g_tileB, 1u);
            __syncthreads();
            const unsigned tile = smem[G_BCAST];
            if (tile >= (unsigned)NTILES) break;
            gemm_tile(smem, X, W, tile);
            __threadfence();
            __syncthreads();
            if (tid == 0) {
                asm volatile("red.release.gpu.global.add.u32 [%0], %1;"
                             :: "l"(&g_qdone[tile >> 9]), "r"(1u) : "memory");
            }
        }
    }
}

// ---------------------------------------------------------------------------
extern "C" void kernel_launch(void* const* d_in, const int* in_sizes, int n_in,
                              void* d_out, int out_size) {
    const float* x  = (const float*)d_in[0];  // [64, 512, 1024]
    const float* w  = (const float*)d_in[1];  // [1024, 1024]
    const float* wr = (const float*)d_in[2];  // [1024, 1024]
    float* out = (float*)d_out;               // [64, 512, 1024]

    cudaFuncSetAttribute(fused_rnn,
                         cudaFuncAttributeMaxDynamicSharedMemorySize,
                         FUSED_SMEM_BYTES);

    reset_state_kernel<<<1, 32>>>();
    fused_rnn<<<NCTA_TOTAL, 512, FUSED_SMEM_BYTES>>>(x, w, wr, out);
}

// round 17
// speedup vs baseline: 1.8083x; 1.0223x over previous
#include <cuda_runtime.h>
#include <cuda_bf16.h>
#include <cstdint>

// ---------------------------------------------------------------------------
// RNN: out[b,t,:] = sigmoid(x@K + h_{t-1}@Wr),  B=64, T=512, D=H=1024
// ONE fused launch, 152 CTAs x 512 threads:
//   Phase A: ALL CTAs drain quarter-0 xh tiles; Phase B: CTAs 0..127 run the
//   recurrence; CTAs 128..151 finish xh quarters 1..3.
// R17: recurrence regrouped exploiting PER-BATCH-ROW INDEPENDENCE:
//   4 independent groups of 32 CTAs; group g owns batch rows [16g, 16g+16);
//   CTA owns 32 N-cols. L2 h-traffic halves (8MB/step), sync domain halves
//   (32-CTA barriers, groups drift independently), per-CTA A-load halves.
//   Warp = K-sixteenth x N=32 (M=16): 32 mma/warp; B frags 3/4 in registers.
// ---------------------------------------------------------------------------

#define BATCH 64
#define TSEQ  512
#define DIM   1024

#define NCTA_TOTAL 152
#define NPERS      128
#define NTILES     2048
#define TILES_PER_Q 512

// ---- recurrence geometry ----
#define NTILE  32                              // N cols per CTA
#define BS_STRIDE 1028
#define BS_WORDS  (NTILE * BS_STRIDE)          // 32896
#define A_STRIDE  68                           // 64 + 4 pad
#define ABUF_WORDS (16 * A_STRIDE)             // 1088: warp buffer 16 rows x 64
#define A_REGION_WORDS (16 * ABUF_WORDS)       // 17408
#define XH_WORDS  512
#define FUSED_SMEM_BYTES ((BS_WORDS + A_REGION_WORDS + XH_WORDS) * 4) // 203,264

// ---- gemm geometry ----
#define G_BM 128
#define G_BN 128
#define G_BK 32
#define GA_STRIDE 36
#define GB_STRIDE 132
#define G_STAGE_WORDS (G_BM * GA_STRIDE + G_BK * GB_STRIDE)   // 8832
#define G_BCAST (2 * G_STAGE_WORDS)

__device__ float g_xh[(size_t)BATCH * TSEQ * DIM];
__device__ unsigned g_tileA;
__device__ unsigned g_tileB;
__device__ unsigned g_qdone[4];
__device__ unsigned g_grp[16];    // 16 subgroup counters (8 CTAs each)
__device__ unsigned g_root[4];    // per-group root counters (4 subgroups)
__device__ unsigned g_sense[4];   // per-group sense

__device__ __forceinline__ uint32_t f2tf32(float x) {
    uint32_t r;
    asm("cvt.rna.tf32.f32 %0, %1;" : "=r"(r) : "f"(x));
    return r;
}

__device__ __forceinline__ void mma_tf32(float* d,
                                         uint32_t a0, uint32_t a1, uint32_t a2, uint32_t a3,
                                         uint32_t b0, uint32_t b1) {
    asm volatile(
        "mma.sync.aligned.m16n8k8.row.col.f32.tf32.tf32.f32 "
        "{%0,%1,%2,%3}, {%4,%5,%6,%7}, {%8,%9}, {%0,%1,%2,%3};\n"
        : "+f"(d[0]), "+f"(d[1]), "+f"(d[2]), "+f"(d[3])
        : "r"(a0), "r"(a1), "r"(a2), "r"(a3), "r"(b0), "r"(b1));
}

__device__ __forceinline__ float sigmoidf_fast(float z) {
    return 1.0f / (1.0f + __expf(-z));
}

__device__ __forceinline__ void cp16(uint32_t smem_addr, const void* gsrc) {
    asm volatile("cp.async.cg.shared.global [%0], [%1], 16;\n"
                 :: "r"(smem_addr), "l"(gsrc));
}
__device__ __forceinline__ void cp_commit() {
    asm volatile("cp.async.commit_group;\n" ::: "memory");
}
template <int N>
__device__ __forceinline__ void cp_wait() {
    asm volatile("cp.async.wait_group %0;\n" :: "n"(N) : "memory");
}

// ---------------------------------------------------------------------------
__global__ void reset_state_kernel() {
    if (threadIdx.x < 16) g_grp[threadIdx.x] = 0u;
    if (threadIdx.x >= 16 && threadIdx.x < 20) g_root[threadIdx.x - 16] = 0u;
    if (threadIdx.x >= 20 && threadIdx.x < 24) g_sense[threadIdx.x - 20] = 0u;
    if (threadIdx.x == 24) g_tileA = 0u;
    if (threadIdx.x == 25) g_tileB = (unsigned)TILES_PER_Q;
    if (threadIdx.x >= 26 && threadIdx.x < 30) g_qdone[threadIdx.x - 26] = 0u;
}

// ---------------------------------------------------------------------------
// Per-group tree barrier over 32 CTAs: 4 subgroups of 8 -> root of 4.
// Counters self-reset; parity sense; groups fully independent.
// ---------------------------------------------------------------------------
__device__ __forceinline__ void group_barrier(int bid, int tid, int t) {
    __syncthreads();
    if (tid == 0) {
        const int grp = bid >> 5;
        const unsigned ns = ((unsigned)t & 1u) ^ 1u;
        __threadfence();
        unsigned old;
        asm volatile("atom.acq_rel.gpu.global.add.u32 %0, [%1], %2;"
                     : "=r"(old) : "l"(&g_grp[bid >> 3]), "r"(1u) : "memory");
        if (old == 7u) {
            asm volatile("st.relaxed.gpu.global.u32 [%0], %1;"
                         :: "l"(&g_grp[bid >> 3]), "r"(0u) : "memory");
            unsigned rold;
            asm volatile("atom.acq_rel.gpu.global.add.u32 %0, [%1], %2;"
                         : "=r"(rold) : "l"(&g_root[grp]), "r"(1u) : "memory");
            if (rold == 3u) {
                asm volatile("st.relaxed.gpu.global.u32 [%0], %1;"
                             :: "l"(&g_root[grp]), "r"(0u) : "memory");
                asm volatile("st.release.gpu.global.u32 [%0], %1;"
                             :: "l"(&g_sense[grp]), "r"(ns) : "memory");
            } else {
                unsigned v;
                do {
                    asm volatile("ld.acquire.gpu.global.u32 %0, [%1];"
                                 : "=r"(v) : "l"(&g_sense[grp]) : "memory");
                } while (v != ns);
            }
        } else {
            unsigned v;
            do {
                asm volatile("ld.acquire.gpu.global.u32 %0, [%1];"
                             : "=r"(v) : "l"(&g_sense[grp]) : "memory");
            } while (v != ns);
        }
    }
    __syncthreads();
}

// ---------------------------------------------------------------------------
// One xh tile: tile = q*512 + b*8 + n -> rows [b*512+q*128, +128), cols n*128.
// ---------------------------------------------------------------------------
__device__ void gemm_tile(uint32_t* gsm, const float* __restrict__ X,
                          const float* __restrict__ W, unsigned tile) {
    const int tid  = threadIdx.x;
    const int lane = tid & 31;
    const int wid  = tid >> 5;
    const int wm   = (wid & 3) * 32;
    const int wn   = (wid >> 2) * 32;
    const int gid  = lane >> 2;
    const int tg   = lane & 3;

    const int q  = (int)(tile >> 9);
    const int j  = (int)(tile & 511);
    const int bm = (j >> 3) * TSEQ + q * 128;
    const int bn = (j & 7) * G_BN;

    auto As = [&](int s) { return gsm + s * G_STAGE_WORDS; };
    auto Bs = [&](int s) { return gsm + s * G_STAGE_WORDS + G_BM * GA_STRIDE; };

    auto issue = [&](int k0, int s) {
        uint32_t abase = (uint32_t)__cvta_generic_to_shared(As(s));
        uint32_t bbase = (uint32_t)__cvta_generic_to_shared(Bs(s));
        #pragma unroll
        for (int i = 0; i < 2; i++) {
            int idx = tid + i * 512;
            int r = idx >> 3;
            int c = (idx & 7) * 4;
            cp16(abase + (r * GA_STRIDE + c) * 4,
                 X + (size_t)(bm + r) * DIM + k0 + c);
        }
        #pragma unroll
        for (int i = 0; i < 2; i++) {
            int idx = tid + i * 512;
            int r = idx >> 5;
            int c = (idx & 31) * 4;
            cp16(bbase + (r * GB_STRIDE + c) * 4,
                 W + (size_t)(k0 + r) * DIM + bn + c);
        }
        cp_commit();
    };

    float acc[2][4][4];
    #pragma unroll
    for (int mt = 0; mt < 2; mt++)
        #pragma unroll
        for (int nt = 0; nt < 4; nt++)
            #pragma unroll
            for (int i = 0; i < 4; i++) acc[mt][nt][i] = 0.0f;

    issue(0, 0);
    issue(G_BK, 1);

    const int NKITER = DIM / G_BK;
    for (int kb = 0; kb < NKITER; kb++) {
        if (kb < NKITER - 1) cp_wait<1>(); else cp_wait<0>();
        __syncthreads();

        const uint32_t* A = As(kb & 1);
        const uint32_t* B = Bs(kb & 1);

        #pragma unroll
        for (int k8 = 0; k8 < G_BK; k8 += 8) {
            uint32_t a[2][4], b[4][2];
            #pragma unroll
            for (int mt = 0; mt < 2; mt++) {
                int r = (wm + mt * 16 + gid) * GA_STRIDE;
                a[mt][0] = A[r + k8 + tg];
                a[mt][1] = A[r + 8 * GA_STRIDE + k8 + tg];
                a[mt][2] = A[r + k8 + tg + 4];
                a[mt][3] = A[r + 8 * GA_STRIDE + k8 + tg + 4];
            }
            #pragma unroll
            for (int nt = 0; nt < 4; nt++) {
                int c = wn + nt * 8 + gid;
                b[nt][0] = B[(k8 + tg) * GB_STRIDE + c];
                b[nt][1] = B[(k8 + tg + 4) * GB_STRIDE + c];
            }
            #pragma unroll
            for (int mt = 0; mt < 2; mt++)
                #pragma unroll
                for (int nt = 0; nt < 4; nt++)
                    mma_tf32(acc[mt][nt], a[mt][0], a[mt][1], a[mt][2], a[mt][3],
                             b[nt][0], b[nt][1]);
        }
        __syncthreads();
        if (kb + 2 < NKITER) issue((kb + 2) * G_BK, kb & 1);
    }

    #pragma unroll
    for (int mt = 0; mt < 2; mt++) {
        #pragma unroll
        for (int nt = 0; nt < 4; nt++) {
            int r = bm + wm + mt * 16 + gid;
            int c = bn + wn + nt * 8 + tg * 2;
            *(float2*)(&g_xh[(size_t)r * DIM + c]) =
                make_float2(acc[mt][nt][0], acc[mt][nt][1]);
            *(float2*)(&g_xh[(size_t)(r + 8) * DIM + c]) =
                make_float2(acc[mt][nt][2], acc[mt][nt][3]);
        }
    }
}

// ---------------------------------------------------------------------------
// Recurrence: CTA bid -> grp = bid>>5 (rows [grp*16, +16)), bn = (bid&31)*32.
// 16 warps = K-sixteenths (64 K each), each covering M=16 x N=32.
// B frags: nt 0..2 in registers (48 regs), nt 3 from SMEM.
// Single A buffer/warp (16 rows x 64 cols). xh prefetch in group-2 cp.async.
// 16-way K-reduction in aliased scratch -> flat epilogue -> group barrier.
// ---------------------------------------------------------------------------
__device__ void pers_path(uint32_t* smem, const float* __restrict__ Wr,
                          float* __restrict__ OUT, int bid) {
    uint32_t* Bsm  = smem;
    uint32_t* Abuf = smem + BS_WORDS;
    float*    Scr  = (float*)Abuf;
    float*    Xhs  = (float*)(smem + BS_WORDS + A_REGION_WORDS);

    const int tid   = threadIdx.x;
    const int lane  = tid & 31;
    const int wid   = tid >> 5;
    const int grp   = bid >> 5;            // 0..3
    const int bn    = (bid & 31) * NTILE;  // N base
    const int rbase = grp * 16;            // batch-row base
    const int ks    = wid;                 // K-sixteenth 0..15
    const int kbase = ks * 64;
    const int gid   = lane >> 2;
    const int tg    = lane & 3;

    // Wr slice -> SMEM transposed [n][k], RNA tf32 (once)
    for (int idx = tid; idx < NTILE * DIM; idx += 512) {
        int n = idx & (NTILE - 1);
        int k = idx >> 5;
        Bsm[n * BS_STRIDE + k] = f2tf32(Wr[(size_t)k * DIM + bn + n]);
    }
    __syncthreads();

    // B fragments nt 0..2 -> registers (held for all 512 steps)
    uint32_t breg[8][3][2];
    #pragma unroll
    for (int k8i = 0; k8i < 8; k8i++) {
        #pragma unroll
        for (int nt = 0; nt < 3; nt++) {
            int n = nt * 8 + gid;
            breg[k8i][nt][0] = Bsm[n * BS_STRIDE + kbase + k8i * 8 + tg];
            breg[k8i][nt][1] = Bsm[n * BS_STRIDE + kbase + k8i * 8 + tg + 4];
        }
    }

    // quarter-0 xh complete before t=0
    if (tid == 0) {
        unsigned v;
        do {
            asm volatile("ld.acquire.gpu.global.u32 %0, [%1];"
                         : "=r"(v) : "l"(&g_qdone[0]) : "memory");
        } while (v < TILES_PER_Q);
    }
    __syncthreads();

    const uint32_t* Aw = Abuf + wid * ABUF_WORDS;
    const uint32_t warp_sb = (uint32_t)__cvta_generic_to_shared(Abuf)
                           + wid * ABUF_WORDS * 4;
    const uint32_t xh_sb = (uint32_t)__cvta_generic_to_shared(Xhs);

    for (int t = 0; t < TSEQ; t++) {
        if ((t & 127) == 0 && t > 0) {
            if (tid == 0) {
                unsigned v;
                do {
                    asm volatile("ld.acquire.gpu.global.u32 %0, [%1];"
                                 : "=r"(v) : "l"(&g_qdone[t >> 7]) : "memory");
                } while (v < TILES_PER_Q);
            }
            __syncthreads();
        }

        float acc[4][4];   // [nt][frag], M=16 single tile
        #pragma unroll
        for (int nt = 0; nt < 4; nt++)
            #pragma unroll
            for (int i = 0; i < 4; i++) acc[nt][i] = 0.0f;

        if (t > 0) {
            const float* Hprev = OUT + (size_t)(t - 1) * DIM;

            // GROUP 1: A load (16 rows x 64 cols = 8 cp16/lane)
            #pragma unroll
            for (int i = 0; i < 8; i++) {
                int idx = lane + i * 32;
                int r  = idx >> 4;        // 0..15
                int c4 = idx & 15;        // 0..15
                cp16(warp_sb + (r * A_STRIDE + c4 * 4) * 4,
                     Hprev + (size_t)(rbase + r) * (TSEQ * DIM) + kbase + c4 * 4);
            }
            cp_commit();

            // GROUP 2: xh prefetch (128 cp16; lanes 0-7 of each warp issue 1)
            if (lane < 8) {
                int idx = wid * 8 + lane;    // 0..127
                int row = idx >> 3;          // 0..15
                int seg = (idx & 7) * 4;     // 0..28
                cp16(xh_sb + (row * 32 + seg) * 4,
                     &g_xh[((size_t)(rbase + row) * TSEQ + t) * DIM + bn + seg]);
            }
            cp_commit();

            cp_wait<1>();    // A landed; xh in flight behind mma
            __syncwarp();

            #pragma unroll
            for (int k8i = 0; k8i < 8; k8i++) {
                const int kk = k8i * 8;
                uint32_t a0 = Aw[gid * A_STRIDE + kk + tg];
                uint32_t a1 = Aw[(gid + 8) * A_STRIDE + kk + tg];
                uint32_t a2 = Aw[gid * A_STRIDE + kk + tg + 4];
                uint32_t a3 = Aw[(gid + 8) * A_STRIDE + kk + tg + 4];
                #pragma unroll
                for (int nt = 0; nt < 3; nt++)
                    mma_tf32(acc[nt], a0, a1, a2, a3,
                             breg[k8i][nt][0], breg[k8i][nt][1]);
                {   // nt = 3 from SMEM
                    int n = 24 + gid;
                    uint32_t b0 = Bsm[n * BS_STRIDE + kbase + kk + tg];
                    uint32_t b1 = Bsm[n * BS_STRIDE + kbase + kk + tg + 4];
                    mma_tf32(acc[3], a0, a1, a2, a3, b0, b1);
                }
            }

            cp_wait<0>();    // xh landed
        }

        __syncthreads();   // compute done before scratch aliases A buffers

        // partial store: P[ks][row 0..15][col 0..31]  (512 floats per ks)
        #pragma unroll
        for (int nt = 0; nt < 4; nt++) {
            int off = ks * 512 + gid * 32 + nt * 8 + tg * 2;
            *(float2*)&Scr[off]       = make_float2(acc[nt][0], acc[nt][1]);
            *(float2*)&Scr[off + 256] = make_float2(acc[nt][2], acc[nt][3]);  // row gid+8
        }
        __syncthreads();

        // flat epilogue: 512 threads x 1 output; xh from SMEM (t>0)
        {
            int o   = tid;
            int row = o >> 5;          // 0..15
            int col = o & 31;          // 0..31
            float s = 0.0f;
            #pragma unroll
            for (int p = 0; p < 16; p++) s += Scr[p * 512 + o];
            size_t go = ((size_t)(rbase + row) * TSEQ + t) * DIM + bn + col;
            float xh = (t > 0) ? Xhs[o] : g_xh[go];
            OUT[go] = sigmoidf_fast(s + xh);
        }

        group_barrier(bid, tid, t);
    }
}

// ---------------------------------------------------------------------------
__global__ __launch_bounds__(512, 1) void fused_rnn(const float* __restrict__ X,
                                                    const float* __restrict__ W,
                                                    const float* __restrict__ Wr,
                                                    float* __restrict__ OUT) {
    extern __shared__ uint32_t smem[];
    const int tid = threadIdx.x;
    const int bid = blockIdx.x;

    // ---- Phase A: all CTAs drain quarter-0 tiles ----
    for (;;) {
        if (tid == 0) smem[G_BCAST] = atomicAdd(&g_tileA, 1u);
        __syncthreads();
        const unsigned tile = smem[G_BCAST];
        if (tile >= (unsigned)TILES_PER_Q) break;
        gemm_tile(smem, X, W, tile);
        __threadfence();
        __syncthreads();
        if (tid == 0) {
            asm volatile("red.release.gpu.global.add.u32 [%0], %1;"
                         :: "l"(&g_qdone[0]), "r"(1u) : "memory");
        }
    }
    __syncthreads();

    if (bid < NPERS) {
        pers_path(smem, Wr, OUT, bid);
    } else {
        for (;;) {
            if (tid == 0) smem[G_BCAST] = atomicAdd(&g_tileB, 1u);
            __syncthreads();
            const unsigned tile = smem[G_BCAST];
            if (tile >= (unsigned)NTILES) break;
            gemm_tile(smem, X, W, tile);
            __threadfence();
            __syncthreads();
            if (tid == 0) {
                asm volatile("red.release.gpu.global.add.u32 [%0], %1;"
                             :: "l"(&g_qdone[tile >> 9]), "r"(1u) : "memory");
            }
        }
    }
}

// ---------------------------------------------------------------------------
extern "C" void kernel_launch(void* const* d_in, const int* in_sizes, int n_in,
                              void* d_out, int out_size) {
    const float* x  = (const float*)d_in[0];  // [64, 512, 1024]
    const float* w  = (const float*)d_in[1];  // [1024, 1024]
    const float* wr = (const float*)d_in[2];  // [1024, 1024]
    float* out = (float*)d_out;               // [64, 512, 1024]

    cudaFuncSetAttribute(fused_rnn,
                         cudaFuncAttributeMaxDynamicSharedMemorySize,
                         FUSED_SMEM_BYTES);

    reset_state_kernel<<<1, 32>>>();
    fused_rnn<<<NCTA_TOTAL, 512, FUSED_SMEM_BYTES>>>(x, w, wr, out);
}